// round 1
// baseline (speedup 1.0000x reference)
#include <cuda_runtime.h>
#include <mma.h>
#include <cstdint>

using namespace nvcuda;

#define BZ  256
#define SRCN 1024
#define DIM 512

#define TM 128
#define TN 128
#define TK 32
#define APITCH 40   // TK + 8 pad -> 160B rows, 32B-aligned wmma loads
#define CPITCH 136  // TN + 8 pad -> 544B rows, 32B-aligned wmma stores

#define SMEM_BYTES (TM * CPITCH * 4 + 2 * TM * 4)   // 69632 + 1024 = 70656

// scratch (no cudaMalloc allowed)
__device__ float g_q_buf[BZ * DIM];     // q = tgt @ W_q^T   (B, D)
__device__ float g_u_buf[BZ * SRCN];    // u = v . tanh(q+r) (B, S)

// ---------------------------------------------------------------------------
// Kernel 1: q[b,e] = sum_d tgt[b,d] * W_q[e,d]
// ---------------------------------------------------------------------------
__global__ void qproj_kernel(const float* __restrict__ tgt,
                             const float* __restrict__ Wq) {
    __shared__ float st[DIM];
    int b = blockIdx.x, tid = threadIdx.x;   // 512 threads, one e each
    st[tid] = tgt[(size_t)b * DIM + tid];
    __syncthreads();
    const float4* w  = reinterpret_cast<const float4*>(Wq + (size_t)tid * DIM);
    const float4* t4 = reinterpret_cast<const float4*>(st);
    float sum = 0.f;
#pragma unroll 8
    for (int i = 0; i < DIM / 4; i++) {
        float4 a = w[i], c = t4[i];
        sum += a.x * c.x + a.y * c.y + a.z * c.z + a.w * c.w;
    }
    g_q_buf[(size_t)b * DIM + tid] = sum;
}

// ---------------------------------------------------------------------------
// Kernel 2: fused tf32 GEMMs over src.
//   blockIdx.y == 0 : r = src @ W_ref^T  -> u[b,s] = sum_e v[e]*tanh(q[b,e]+r)
//   blockIdx.y == 1 : h = src @ conv_w^T -> attn_h[b,o,s] = h[s,o] + conv_b[o]
// CTA tile: 128 rows (s) x 128 cols (e/o), looped over 4 col-chunks, K=512.
// ---------------------------------------------------------------------------
extern __shared__ float smem[];

__global__ void __launch_bounds__(256, 2)
fused_gemm_kernel(const float* __restrict__ src,
                  const float* __restrict__ W_ref,
                  const float* __restrict__ conv_w,
                  const float* __restrict__ conv_b,
                  const float* __restrict__ v,
                  float* __restrict__ out_attn) {
    float* sA = smem;                     // TM x APITCH
    float* sB = smem + TM * APITCH;       // TN x APITCH
    float* sC = smem;                     // TM x CPITCH (reuses A/B region)
    float* sQ = smem + TM * CPITCH;       // 128 floats (q chunk or conv_b chunk)
    float* sV = sQ + TM;                  // 128 floats (v chunk)

    const int tile = blockIdx.x;
    const int b  = tile >> 3;
    const int s0 = (tile & 7) * TM;
    const int gemm = blockIdx.y;

    const int tid  = threadIdx.x;
    const int warp = tid >> 5;
    const int wm   = warp & 3;    // 4 row-blocks of 32
    const int wn   = warp >> 2;   // 2 col-blocks of 64

    const float* gA = src + ((size_t)b * SRCN + s0) * DIM;
    const float* W  = (gemm == 0) ? W_ref : conv_w;

    const int lr = tid >> 3;        // 0..31
    const int lc = (tid & 7) * 4;   // 0..28 step 4

    float u_acc = 0.f;

    for (int nc = 0; nc < 4; nc++) {
        const int e0 = nc * TN;

        wmma::fragment<wmma::accumulator, 16, 16, 8, float> c[2][4];
#pragma unroll
        for (int i = 0; i < 2; i++)
#pragma unroll
            for (int j = 0; j < 4; j++) wmma::fill_fragment(c[i][j], 0.f);

        for (int kt = 0; kt < DIM / TK; kt++) {
            const int k0 = kt * TK;
            __syncthreads();   // smem free from previous phase
#pragma unroll
            for (int p = 0; p < 4; p++) {
                int r = lr + p * 32;
                float4 a = *reinterpret_cast<const float4*>(gA + (size_t)r * DIM + k0 + lc);
                *reinterpret_cast<float4*>(sA + r * APITCH + lc) = a;
            }
#pragma unroll
            for (int p = 0; p < 4; p++) {
                int r = lr + p * 32;
                float4 w4 = *reinterpret_cast<const float4*>(W + (size_t)(e0 + r) * DIM + k0 + lc);
                *reinterpret_cast<float4*>(sB + r * APITCH + lc) = w4;
            }
            __syncthreads();

#pragma unroll
            for (int kk = 0; kk < TK / 8; kk++) {
                wmma::fragment<wmma::matrix_a, 16, 16, 8, wmma::precision::tf32, wmma::row_major> a[2];
                wmma::fragment<wmma::matrix_b, 16, 16, 8, wmma::precision::tf32, wmma::col_major> bf[4];
#pragma unroll
                for (int i = 0; i < 2; i++) {
                    wmma::load_matrix_sync(a[i], sA + (wm * 32 + i * 16) * APITCH + kk * 8, APITCH);
#pragma unroll
                    for (int t = 0; t < a[i].num_elements; t++)
                        a[i].x[t] = wmma::__float_to_tf32(a[i].x[t]);
                }
#pragma unroll
                for (int j = 0; j < 4; j++) {
                    wmma::load_matrix_sync(bf[j], sB + (wn * 64 + j * 16) * APITCH + kk * 8, APITCH);
#pragma unroll
                    for (int t = 0; t < bf[j].num_elements; t++)
                        bf[j].x[t] = wmma::__float_to_tf32(bf[j].x[t]);
                }
#pragma unroll
                for (int i = 0; i < 2; i++)
#pragma unroll
                    for (int j = 0; j < 4; j++)
                        wmma::mma_sync(c[i][j], a[i], bf[j], c[i][j]);
            }
        }
        __syncthreads();   // mma done reading sA/sB; safe to overwrite with sC

#pragma unroll
        for (int i = 0; i < 2; i++)
#pragma unroll
            for (int j = 0; j < 4; j++)
                wmma::store_matrix_sync(sC + (wm * 32 + i * 16) * CPITCH + wn * 64 + j * 16,
                                        c[i][j], CPITCH, wmma::mem_row_major);

        if (gemm == 0) {
            if (tid < TN) {
                sQ[tid] = g_q_buf[(size_t)b * DIM + e0 + tid];
                sV[tid] = v[e0 + tid];
            }
            __syncthreads();
            const int row = tid >> 1;
            const int cb  = (tid & 1) * 64;
            float part = 0.f;
#pragma unroll 4
            for (int i = 0; i < 64; i++) {
                float rr = sC[row * CPITCH + cb + i];
                part += sV[cb + i] * tanhf(sQ[cb + i] + rr);
            }
            part += __shfl_xor_sync(0xffffffffu, part, 1);
            u_acc += part;
            __syncthreads();
        } else {
            if (tid < TN) sQ[tid] = conv_b[e0 + tid];
            __syncthreads();
            for (int idx = tid; idx < TM * TN; idx += 256) {
                int o = idx >> 7;
                int s = idx & 127;
                out_attn[((size_t)b * DIM + e0 + o) * SRCN + s0 + s] = sC[s * CPITCH + o] + sQ[o];
            }
            __syncthreads();
        }
    }

    if (gemm == 0 && (tid & 1) == 0) {
        int row = tid >> 1;
        g_u_buf[(size_t)b * SRCN + s0 + row] = u_acc;
    }
}

// ---------------------------------------------------------------------------
// Kernel 3: score = C*tanh(u), mask (input mask OR s==prev), softmax,
// write logits and mask_ (as 0/1 float) into out tail.
// ---------------------------------------------------------------------------
__global__ void softmax_kernel(const uint8_t* __restrict__ mask_in,
                               const int* __restrict__ prev,
                               float* __restrict__ out,
                               int has_logits, int has_mask) {
    __shared__ float red[256];
    const int b = blockIdx.x, tid = threadIdx.x;
    const int p = prev[b];

    float sc[4];
    bool  ms[4];
    float mx = -3.0e38f;
#pragma unroll
    for (int j = 0; j < 4; j++) {
        int s = tid + j * 256;
        float u = g_u_buf[(size_t)b * SRCN + s];
        bool m = (mask_in[(size_t)b * SRCN + s] != 0) || (s == p);
        ms[j] = m;
        float val = m ? -3.0e38f : 10.f * tanhf(u);
        sc[j] = val;
        mx = fmaxf(mx, val);
    }
    red[tid] = mx; __syncthreads();
    for (int o = 128; o > 0; o >>= 1) {
        if (tid < o) red[tid] = fmaxf(red[tid], red[tid + o]);
        __syncthreads();
    }
    mx = red[0];
    __syncthreads();

    float e[4], se = 0.f;
#pragma unroll
    for (int j = 0; j < 4; j++) {
        e[j] = ms[j] ? 0.f : expf(sc[j] - mx);
        se += e[j];
    }
    red[tid] = se; __syncthreads();
    for (int o = 128; o > 0; o >>= 1) {
        if (tid < o) red[tid] += red[tid + o];
        __syncthreads();
    }
    const float inv = 1.f / red[0];

    const size_t attn = (size_t)BZ * DIM * SRCN;
#pragma unroll
    for (int j = 0; j < 4; j++) {
        int s = tid + j * 256;
        if (has_logits) out[attn + (size_t)b * SRCN + s] = e[j] * inv;
        if (has_mask)   out[attn + (size_t)BZ * SRCN + (size_t)b * SRCN + s] = ms[j] ? 1.f : 0.f;
    }
}

// ---------------------------------------------------------------------------
extern "C" void kernel_launch(void* const* d_in, const int* in_sizes, int n_in,
                              void* d_out, int out_size) {
    (void)in_sizes; (void)n_in;
    const float*   src    = (const float*)d_in[0];
    const float*   tgt    = (const float*)d_in[1];
    const uint8_t* mask   = (const uint8_t*)d_in[2];
    const int*     prev   = (const int*)d_in[3];
    const float*   W_q    = (const float*)d_in[4];
    const float*   W_ref  = (const float*)d_in[5];
    const float*   v      = (const float*)d_in[6];
    const float*   conv_w = (const float*)d_in[7];
    const float*   conv_b = (const float*)d_in[8];
    float* out = (float*)d_out;

    const size_t attn = (size_t)BZ * DIM * SRCN;
    const size_t row  = (size_t)BZ * SRCN;
    int has_logits = ((size_t)out_size >= attn + row)     ? 1 : 0;
    int has_mask   = ((size_t)out_size >= attn + 2 * row) ? 1 : 0;

    cudaFuncSetAttribute(fused_gemm_kernel,
                         cudaFuncAttributeMaxDynamicSharedMemorySize, SMEM_BYTES);

    qproj_kernel<<<BZ, DIM>>>(tgt, W_q);

    dim3 grid(BZ * 8, 2);
    fused_gemm_kernel<<<grid, 256, SMEM_BYTES>>>(src, W_ref, conv_w, conv_b, v, out);

    softmax_kernel<<<BZ, 256>>>(mask, prev, out, has_logits, has_mask);
}

// round 3
// speedup vs baseline: 3.0772x; 3.0772x over previous
#include <cuda_runtime.h>
#include <cuda_fp16.h>
#include <cstdint>

#define BZ   256
#define SRCN 1024
#define DIM  512

// ---------------------------------------------------------------------------
// scratch (no cudaMalloc allowed)
// ---------------------------------------------------------------------------
__device__ __align__(16) __half g_src16[(size_t)BZ * SRCN * DIM];   // 268 MB
__device__ __align__(16) __half g_w16[1024 * DIM];                  // W_ref rows 0-511, conv_w rows 512-1023
__device__ __align__(16) float  g_q_buf[BZ * DIM];
__device__ __align__(16) float  g_u_part[(size_t)BZ * SRCN * 8];    // 8 partials per (b,s)

// ---------------------------------------------------------------------------
// helpers
// ---------------------------------------------------------------------------
__device__ __forceinline__ uint32_t smem_u32(const void* p) {
    uint32_t a;
    asm("{ .reg .u64 t; cvta.to.shared.u64 t, %1; cvt.u32.u64 %0, t; }" : "=r"(a) : "l"(p));
    return a;
}

#define CP_ASYNC16(dst, src) \
    asm volatile("cp.async.cg.shared.global [%0], [%1], 16;" :: "r"(dst), "l"(src))
#define CP_COMMIT() asm volatile("cp.async.commit_group;" ::: "memory")
#define CP_WAIT2()  asm volatile("cp.async.wait_group 2;" ::: "memory")

__device__ __forceinline__ void ldsm4(uint32_t& r0, uint32_t& r1, uint32_t& r2, uint32_t& r3,
                                      uint32_t addr) {
    asm volatile("ldmatrix.sync.aligned.m8n8.x4.shared.b16 {%0,%1,%2,%3}, [%4];"
                 : "=r"(r0), "=r"(r1), "=r"(r2), "=r"(r3) : "r"(addr));
}

__device__ __forceinline__ void mma_f16(float* c, uint32_t a0, uint32_t a1, uint32_t a2, uint32_t a3,
                                        uint32_t b0, uint32_t b1) {
    asm volatile("mma.sync.aligned.m16n8k16.row.col.f32.f16.f16.f32 "
                 "{%0,%1,%2,%3}, {%4,%5,%6,%7}, {%8,%9}, {%0,%1,%2,%3};"
                 : "+f"(c[0]), "+f"(c[1]), "+f"(c[2]), "+f"(c[3])
                 : "r"(a0), "r"(a1), "r"(a2), "r"(a3), "r"(b0), "r"(b1));
}

// fast tanh (MUFU-based), ~1e-6 abs err
__device__ __forceinline__ float ftanh(float x) {
    float e = __expf(2.0f * x);
    return 1.0f - __fdividef(2.0f, e + 1.0f);
}

// ---------------------------------------------------------------------------
// convert fp32 -> fp16 (src + both weight matrices)
// ---------------------------------------------------------------------------
#define SRC_ELEMS ((size_t)BZ * SRCN * DIM)   // 134217728
#define W_ELEMS   (512 * 512)                 // per weight matrix

__global__ void __launch_bounds__(256) convert_kernel(const float* __restrict__ src,
                                                      const float* __restrict__ W_ref,
                                                      const float* __restrict__ conv_w) {
    size_t gid = (size_t)blockIdx.x * 256 + threadIdx.x;
    size_t i8 = gid * 8;
    if (i8 < SRC_ELEMS) {
        float4 x0 = *reinterpret_cast<const float4*>(src + i8);
        float4 x1 = *reinterpret_cast<const float4*>(src + i8 + 4);
        __half2 h0 = __floats2half2_rn(x0.x, x0.y);
        __half2 h1 = __floats2half2_rn(x0.z, x0.w);
        __half2 h2 = __floats2half2_rn(x1.x, x1.y);
        __half2 h3 = __floats2half2_rn(x1.z, x1.w);
        uint4 o = make_uint4(*(uint32_t*)&h0, *(uint32_t*)&h1, *(uint32_t*)&h2, *(uint32_t*)&h3);
        *reinterpret_cast<uint4*>(g_src16 + i8) = o;
    } else {
        size_t w8 = i8 - SRC_ELEMS;
        if (w8 < 2 * (size_t)W_ELEMS) {
            const float* wsrc = (w8 < W_ELEMS) ? (W_ref + w8) : (conv_w + (w8 - W_ELEMS));
            float4 x0 = *reinterpret_cast<const float4*>(wsrc);
            float4 x1 = *reinterpret_cast<const float4*>(wsrc + 4);
            __half2 h0 = __floats2half2_rn(x0.x, x0.y);
            __half2 h1 = __floats2half2_rn(x0.z, x0.w);
            __half2 h2 = __floats2half2_rn(x1.x, x1.y);
            __half2 h3 = __floats2half2_rn(x1.z, x1.w);
            uint4 o = make_uint4(*(uint32_t*)&h0, *(uint32_t*)&h1, *(uint32_t*)&h2, *(uint32_t*)&h3);
            *reinterpret_cast<uint4*>(g_w16 + w8) = o;
        }
    }
}

// ---------------------------------------------------------------------------
// qproj: q[b,e] = sum_d tgt[b,d] * W_q[e,d]   (fp32, tiny)
// ---------------------------------------------------------------------------
__global__ void __launch_bounds__(512) qproj_kernel(const float* __restrict__ tgt,
                                                    const float* __restrict__ Wq) {
    __shared__ float st[4 * DIM];
    const int b0 = blockIdx.x * 4;
    const int tid = threadIdx.x;
    for (int i = tid; i < 4 * DIM; i += 512) st[i] = tgt[(size_t)b0 * DIM + i];
    __syncthreads();
    const float4* w = reinterpret_cast<const float4*>(Wq + (size_t)tid * DIM);
    const float4* t0 = reinterpret_cast<const float4*>(st);
    const float4* t1 = reinterpret_cast<const float4*>(st + DIM);
    const float4* t2 = reinterpret_cast<const float4*>(st + 2 * DIM);
    const float4* t3 = reinterpret_cast<const float4*>(st + 3 * DIM);
    float a0 = 0.f, a1 = 0.f, a2 = 0.f, a3 = 0.f;
#pragma unroll 4
    for (int i = 0; i < DIM / 4; i++) {
        float4 wv = w[i];
        float4 c;
        c = t0[i]; a0 += wv.x*c.x + wv.y*c.y + wv.z*c.z + wv.w*c.w;
        c = t1[i]; a1 += wv.x*c.x + wv.y*c.y + wv.z*c.z + wv.w*c.w;
        c = t2[i]; a2 += wv.x*c.x + wv.y*c.y + wv.z*c.z + wv.w*c.w;
        c = t3[i]; a3 += wv.x*c.x + wv.y*c.y + wv.z*c.z + wv.w*c.w;
    }
    g_q_buf[(size_t)(b0 + 0) * DIM + tid] = a0;
    g_q_buf[(size_t)(b0 + 1) * DIM + tid] = a1;
    g_q_buf[(size_t)(b0 + 2) * DIM + tid] = a2;
    g_q_buf[(size_t)(b0 + 3) * DIM + tid] = a3;
}

// ---------------------------------------------------------------------------
// main GEMM: per CTA 128(M=s) x 128(N=e/o), K=512, fp16 mma.sync + cp.async
// grid: (64, 256): y = batch, x = nt*8 + mt;  nt 0-3 -> W_ref, 4-7 -> conv_w
// ---------------------------------------------------------------------------
#define STAGES      4
#define STAGE_BYTES 16384          // A 8KB + B 8KB
#define SM_C        (STAGES * STAGE_BYTES)            // 65536
#define C_PITCH     132
#define SM_QV       (SM_C + 128 * C_PITCH * 4)        // 133120
#define SMEM_TOTAL  (SM_QV + 2 * 512)                 // 134144

extern __shared__ char dsm[];

__global__ void __launch_bounds__(256, 1)
gemm_kernel(const float* __restrict__ conv_b,
            const float* __restrict__ v,
            float* __restrict__ out_attn) {
    const uint32_t smb = smem_u32(dsm);
    const int tid  = threadIdx.x;
    const int wid  = tid >> 5;
    const int lane = tid & 31;
    const int wm   = wid & 3;          // 4 m-groups of 32 rows
    const int wn   = wid >> 2;         // 2 n-groups of 64 cols

    const int b  = blockIdx.y;
    const int nt = blockIdx.x >> 3;
    const int mt = blockIdx.x & 7;
    const int s0 = mt * 128;
    const int n0 = nt * 128;           // global row into stacked weights
    const bool is_ref = (nt < 4);

    float* sQ = reinterpret_cast<float*>(dsm + SM_QV);
    float* sV = sQ + 512 / 4 * 0 + 128;  // second 128-float slot
    float* sC = reinterpret_cast<float*>(dsm + SM_C);

    // stage per-CTA epilogue constants
    if (tid < 128) {
        if (is_ref) {
            sQ[tid] = g_q_buf[(size_t)b * DIM + n0 + tid];
            sV[tid] = v[n0 + tid];
        } else {
            sQ[tid] = conv_b[(n0 - 512) + tid];
        }
    }

    const __half* gA = g_src16 + ((size_t)b * SRCN + s0) * DIM;
    const __half* gB = g_w16 + (size_t)n0 * DIM;

    // cp.async per-thread coords
    const int crow = tid >> 2;         // 0..63
    const int cch  = tid & 3;          // 16B chunk in 64B row

    // accumulators: c[i][j][4], i=m16 tile (2), j=n8 tile (8)
    float cacc[2][8][4];
#pragma unroll
    for (int i = 0; i < 2; i++)
#pragma unroll
        for (int j = 0; j < 8; j++)
#pragma unroll
            for (int r = 0; r < 4; r++) cacc[i][j][r] = 0.f;

    // ldmatrix lane components
    const int a_rl = lane & 15;
    const int a_ch = lane >> 4;
    const int b_rl = (lane & 7) | (((lane >> 4) & 1) << 3);
    const int b_ch = (lane >> 3) & 1;

    // A rows for this warp's two m16 tiles
    const int arow0 = wm * 32 + a_rl;
    const int arow1 = arow0 + 16;
    const int ax0 = (arow0 >> 1) & 3;
    const int ax1 = (arow1 >> 1) & 3;

    auto load_stage = [&](int st, int kt) {
        uint32_t base = smb + st * STAGE_BYTES;
        const __half* ga = gA + kt * 32;
        const __half* gb = gB + kt * 32;
#pragma unroll
        for (int p = 0; p < 2; p++) {
            int r = crow + p * 64;
            int swc = cch ^ ((r >> 1) & 3);
            CP_ASYNC16(base + r * 64 + swc * 16, ga + (size_t)r * DIM + cch * 8);
        }
#pragma unroll
        for (int p = 0; p < 2; p++) {
            int r = crow + p * 64;
            int swc = cch ^ ((r >> 1) & 3);
            CP_ASYNC16(base + 8192 + r * 64 + swc * 16, gb + (size_t)r * DIM + cch * 8);
        }
    };

    // prefetch 3 stages
    load_stage(0, 0); CP_COMMIT();
    load_stage(1, 1); CP_COMMIT();
    load_stage(2, 2); CP_COMMIT();

    for (int kt = 0; kt < 16; kt++) {
        CP_WAIT2();
        __syncthreads();
        if (kt + 3 < 16) load_stage((kt + 3) & 3, kt + 3);
        CP_COMMIT();

        uint32_t abase = smb + (kt & 3) * STAGE_BYTES;
        uint32_t bbase = abase + 8192;

#pragma unroll
        for (int kk = 0; kk < 2; kk++) {
            uint32_t a[2][4];
            {
                int c0 = (kk * 2 + a_ch) ^ ax0;
                ldsm4(a[0][0], a[0][1], a[0][2], a[0][3], abase + arow0 * 64 + c0 * 16);
                int c1 = (kk * 2 + a_ch) ^ ax1;
                ldsm4(a[1][0], a[1][1], a[1][2], a[1][3], abase + arow1 * 64 + c1 * 16);
            }
            uint32_t bb[4][4];
#pragma unroll
            for (int jj = 0; jj < 4; jj++) {
                int brow = wn * 64 + jj * 16 + b_rl;
                int c = (kk * 2 + b_ch) ^ ((brow >> 1) & 3);
                ldsm4(bb[jj][0], bb[jj][1], bb[jj][2], bb[jj][3], bbase + brow * 64 + c * 16);
            }
#pragma unroll
            for (int i = 0; i < 2; i++)
#pragma unroll
                for (int j = 0; j < 8; j++) {
                    int jj = j >> 1;
                    if (j & 1)
                        mma_f16(cacc[i][j], a[i][0], a[i][1], a[i][2], a[i][3], bb[jj][2], bb[jj][3]);
                    else
                        mma_f16(cacc[i][j], a[i][0], a[i][1], a[i][2], a[i][3], bb[jj][0], bb[jj][1]);
                }
        }
    }
    __syncthreads();

    // ------------------------- epilogues -------------------------
    if (is_ref) {
        // u partial: sum_e v[e]*tanh(q[e] + r[s,e]) over this CTA's 128 e-cols
        const int q = lane >> 2;
        const int cl = (lane & 3) * 2;
#pragma unroll
        for (int i = 0; i < 2; i++) {
            float p0 = 0.f, p1 = 0.f;   // rows r and r+8
#pragma unroll
            for (int j = 0; j < 8; j++) {
                int el = wn * 64 + j * 8 + cl;
                float v0 = sV[el], v1 = sV[el + 1];
                float q0 = sQ[el], q1 = sQ[el + 1];
                p0 += v0 * ftanh(q0 + cacc[i][j][0]) + v1 * ftanh(q1 + cacc[i][j][1]);
                p1 += v0 * ftanh(q0 + cacc[i][j][2]) + v1 * ftanh(q1 + cacc[i][j][3]);
            }
            p0 += __shfl_xor_sync(0xffffffffu, p0, 1);
            p0 += __shfl_xor_sync(0xffffffffu, p0, 2);
            p1 += __shfl_xor_sync(0xffffffffu, p1, 1);
            p1 += __shfl_xor_sync(0xffffffffu, p1, 2);
            if ((lane & 3) == 0) {
                int r0 = wm * 32 + i * 16 + q;
                size_t idx = (((size_t)b * SRCN + s0 + r0) << 3) + nt * 2 + wn;
                g_u_part[idx] = p0;
                g_u_part[idx + (8ull << 3)] = p1;   // row r0+8 -> +8 rows * 8 parts
            }
        }
    } else {
        // transpose via smem, write out[(b*512+o)*1024 + s] + bias
        const int q = lane >> 2;
        const int cl = (lane & 3) * 2;
#pragma unroll
        for (int i = 0; i < 2; i++) {
            int r0 = wm * 32 + i * 16 + q;
#pragma unroll
            for (int j = 0; j < 8; j++) {
                int o = wn * 64 + j * 8 + cl;
                sC[o * C_PITCH + r0]           = cacc[i][j][0];
                sC[(o + 1) * C_PITCH + r0]     = cacc[i][j][1];
                sC[o * C_PITCH + r0 + 8]       = cacc[i][j][2];
                sC[(o + 1) * C_PITCH + r0 + 8] = cacc[i][j][3];
            }
        }
        __syncthreads();
        const int o0 = n0 - 512;
        float* outb = out_attn + ((size_t)b * DIM + o0) * SRCN + s0;
#pragma unroll 4
        for (int it = tid; it < 128 * 32; it += 256) {
            int o = it >> 5;
            int sq = (it & 31) * 4;
            float4 val = *reinterpret_cast<const float4*>(sC + o * C_PITCH + sq);
            float bias = sQ[o];
            val.x += bias; val.y += bias; val.z += bias; val.w += bias;
            *reinterpret_cast<float4*>(outb + (size_t)o * SRCN + sq) = val;
        }
    }
}

// ---------------------------------------------------------------------------
// softmax: u = sum(8 partials); score=C*tanh(u); mask; softmax; outputs
// ---------------------------------------------------------------------------
__global__ void softmax_kernel(const uint8_t* __restrict__ mask_in,
                               const int* __restrict__ prev,
                               float* __restrict__ out,
                               int has_logits, int has_mask) {
    __shared__ float red[256];
    const int b = blockIdx.x, tid = threadIdx.x;
    const int p = prev[b];

    float sc[4];
    bool  ms[4];
    float mx = -3.0e38f;
#pragma unroll
    for (int j = 0; j < 4; j++) {
        int s = tid + j * 256;
        const float* up = g_u_part + (((size_t)b * SRCN + s) << 3);
        float u = 0.f;
#pragma unroll
        for (int k = 0; k < 8; k++) u += up[k];
        bool m = (mask_in[(size_t)b * SRCN + s] != 0) || (s == p);
        ms[j] = m;
        float val = m ? -3.0e38f : 10.f * tanhf(u);
        sc[j] = val;
        mx = fmaxf(mx, val);
    }
    red[tid] = mx; __syncthreads();
    for (int o = 128; o > 0; o >>= 1) {
        if (tid < o) red[tid] = fmaxf(red[tid], red[tid + o]);
        __syncthreads();
    }
    mx = red[0];
    __syncthreads();

    float e[4], se = 0.f;
#pragma unroll
    for (int j = 0; j < 4; j++) {
        e[j] = ms[j] ? 0.f : expf(sc[j] - mx);
        se += e[j];
    }
    red[tid] = se; __syncthreads();
    for (int o = 128; o > 0; o >>= 1) {
        if (tid < o) red[tid] += red[tid + o];
        __syncthreads();
    }
    const float inv = 1.f / red[0];

    const size_t attn = (size_t)BZ * DIM * SRCN;
#pragma unroll
    for (int j = 0; j < 4; j++) {
        int s = tid + j * 256;
        if (has_logits) out[attn + (size_t)b * SRCN + s] = e[j] * inv;
        if (has_mask)   out[attn + (size_t)BZ * SRCN + (size_t)b * SRCN + s] = ms[j] ? 1.f : 0.f;
    }
}

// ---------------------------------------------------------------------------
extern "C" void kernel_launch(void* const* d_in, const int* in_sizes, int n_in,
                              void* d_out, int out_size) {
    (void)in_sizes; (void)n_in;
    const float*   src    = (const float*)d_in[0];
    const float*   tgt    = (const float*)d_in[1];
    const uint8_t* mask   = (const uint8_t*)d_in[2];
    const int*     prev   = (const int*)d_in[3];
    const float*   W_q    = (const float*)d_in[4];
    const float*   W_ref  = (const float*)d_in[5];
    const float*   v      = (const float*)d_in[6];
    const float*   conv_w = (const float*)d_in[7];
    const float*   conv_b = (const float*)d_in[8];
    float* out = (float*)d_out;

    const size_t attn = (size_t)BZ * DIM * SRCN;
    const size_t row  = (size_t)BZ * SRCN;
    int has_logits = ((size_t)out_size >= attn + row)     ? 1 : 0;
    int has_mask   = ((size_t)out_size >= attn + 2 * row) ? 1 : 0;

    cudaFuncSetAttribute(gemm_kernel,
                         cudaFuncAttributeMaxDynamicSharedMemorySize, SMEM_TOTAL);

    // 134217728/8 = 16777216 src vecs + 65536 weight vecs -> 65792 blocks
    convert_kernel<<<65792, 256>>>(src, W_ref, conv_w);
    qproj_kernel<<<64, 512>>>(tgt, W_q);

    dim3 grid(64, BZ);
    gemm_kernel<<<grid, 256, SMEM_TOTAL>>>(conv_b, v, out);

    softmax_kernel<<<BZ, 256>>>(mask, prev, out, has_logits, has_mask);
}

// round 4
// speedup vs baseline: 4.3346x; 1.4086x over previous
#include <cuda_runtime.h>
#include <cuda_fp16.h>
#include <cstdint>

#define BZ   256
#define SRCN 1024
#define DIM  512

// ---------------------------------------------------------------------------
// scratch (no cudaMalloc allowed)
// ---------------------------------------------------------------------------
__device__ __align__(16) __half g_src16[(size_t)BZ * SRCN * DIM];   // 268 MB
__device__ __align__(16) __half g_w16[1024 * DIM];                  // W_ref 0-511, conv_w 512-1023
__device__ __align__(16) float  g_q_buf[BZ * DIM];
__device__ __align__(16) float  g_u_part[(size_t)BZ * SRCN * 8];    // 8 partials per (b,s)

// ---------------------------------------------------------------------------
// helpers
// ---------------------------------------------------------------------------
__device__ __forceinline__ uint32_t smem_u32(const void* p) {
    uint32_t a;
    asm("{ .reg .u64 t; cvta.to.shared.u64 t, %1; cvt.u32.u64 %0, t; }" : "=r"(a) : "l"(p));
    return a;
}

#define CP_ASYNC16(dst, src) \
    asm volatile("cp.async.cg.shared.global [%0], [%1], 16;" :: "r"(dst), "l"(src))
#define CP_COMMIT() asm volatile("cp.async.commit_group;" ::: "memory")
#define CP_WAIT2()  asm volatile("cp.async.wait_group 2;" ::: "memory")

__device__ __forceinline__ void ldsm4(uint32_t& r0, uint32_t& r1, uint32_t& r2, uint32_t& r3,
                                      uint32_t addr) {
    asm volatile("ldmatrix.sync.aligned.m8n8.x4.shared.b16 {%0,%1,%2,%3}, [%4];"
                 : "=r"(r0), "=r"(r1), "=r"(r2), "=r"(r3) : "r"(addr));
}

__device__ __forceinline__ void mma_f16(float* c, uint32_t a0, uint32_t a1, uint32_t a2, uint32_t a3,
                                        uint32_t b0, uint32_t b1) {
    asm volatile("mma.sync.aligned.m16n8k16.row.col.f32.f16.f16.f32 "
                 "{%0,%1,%2,%3}, {%4,%5,%6,%7}, {%8,%9}, {%0,%1,%2,%3};"
                 : "+f"(c[0]), "+f"(c[1]), "+f"(c[2]), "+f"(c[3])
                 : "r"(a0), "r"(a1), "r"(a2), "r"(a3), "r"(b0), "r"(b1));
}

__device__ __forceinline__ float ftanh(float x) {
    float e = __expf(2.0f * x);
    return 1.0f - __fdividef(2.0f, e + 1.0f);
}

// ---------------------------------------------------------------------------
// convert fp32 -> fp16 (src + both weight matrices)
// ---------------------------------------------------------------------------
#define SRC_ELEMS ((size_t)BZ * SRCN * DIM)
#define W_ELEMS   (512 * 512)

__global__ void __launch_bounds__(256) convert_kernel(const float* __restrict__ src,
                                                      const float* __restrict__ W_ref,
                                                      const float* __restrict__ conv_w) {
    size_t gid = (size_t)blockIdx.x * 256 + threadIdx.x;
    size_t i8 = gid * 8;
    if (i8 < SRC_ELEMS) {
        float4 x0 = *reinterpret_cast<const float4*>(src + i8);
        float4 x1 = *reinterpret_cast<const float4*>(src + i8 + 4);
        __half2 h0 = __floats2half2_rn(x0.x, x0.y);
        __half2 h1 = __floats2half2_rn(x0.z, x0.w);
        __half2 h2 = __floats2half2_rn(x1.x, x1.y);
        __half2 h3 = __floats2half2_rn(x1.z, x1.w);
        uint4 o = make_uint4(*(uint32_t*)&h0, *(uint32_t*)&h1, *(uint32_t*)&h2, *(uint32_t*)&h3);
        *reinterpret_cast<uint4*>(g_src16 + i8) = o;
    } else {
        size_t w8 = i8 - SRC_ELEMS;
        if (w8 < 2 * (size_t)W_ELEMS) {
            const float* wsrc = (w8 < W_ELEMS) ? (W_ref + w8) : (conv_w + (w8 - W_ELEMS));
            float4 x0 = *reinterpret_cast<const float4*>(wsrc);
            float4 x1 = *reinterpret_cast<const float4*>(wsrc + 4);
            __half2 h0 = __floats2half2_rn(x0.x, x0.y);
            __half2 h1 = __floats2half2_rn(x0.z, x0.w);
            __half2 h2 = __floats2half2_rn(x1.x, x1.y);
            __half2 h3 = __floats2half2_rn(x1.z, x1.w);
            uint4 o = make_uint4(*(uint32_t*)&h0, *(uint32_t*)&h1, *(uint32_t*)&h2, *(uint32_t*)&h3);
            *reinterpret_cast<uint4*>(g_w16 + w8) = o;
        }
    }
}

// ---------------------------------------------------------------------------
// qproj: q[b,e] = sum_d tgt[b,d] * W_q[e,d]
// ---------------------------------------------------------------------------
__global__ void __launch_bounds__(512) qproj_kernel(const float* __restrict__ tgt,
                                                    const float* __restrict__ Wq) {
    __shared__ float st[4 * DIM];
    const int b0 = blockIdx.x * 4;
    const int tid = threadIdx.x;
    for (int i = tid; i < 4 * DIM; i += 512) st[i] = tgt[(size_t)b0 * DIM + i];
    __syncthreads();
    const float4* w = reinterpret_cast<const float4*>(Wq + (size_t)tid * DIM);
    const float4* t0 = reinterpret_cast<const float4*>(st);
    const float4* t1 = reinterpret_cast<const float4*>(st + DIM);
    const float4* t2 = reinterpret_cast<const float4*>(st + 2 * DIM);
    const float4* t3 = reinterpret_cast<const float4*>(st + 3 * DIM);
    float a0 = 0.f, a1 = 0.f, a2 = 0.f, a3 = 0.f;
#pragma unroll 4
    for (int i = 0; i < DIM / 4; i++) {
        float4 wv = w[i];
        float4 c;
        c = t0[i]; a0 += wv.x*c.x + wv.y*c.y + wv.z*c.z + wv.w*c.w;
        c = t1[i]; a1 += wv.x*c.x + wv.y*c.y + wv.z*c.z + wv.w*c.w;
        c = t2[i]; a2 += wv.x*c.x + wv.y*c.y + wv.z*c.z + wv.w*c.w;
        c = t3[i]; a3 += wv.x*c.x + wv.y*c.y + wv.z*c.z + wv.w*c.w;
    }
    g_q_buf[(size_t)(b0 + 0) * DIM + tid] = a0;
    g_q_buf[(size_t)(b0 + 1) * DIM + tid] = a1;
    g_q_buf[(size_t)(b0 + 2) * DIM + tid] = a2;
    g_q_buf[(size_t)(b0 + 3) * DIM + tid] = a3;
}

// ---------------------------------------------------------------------------
// main GEMM: per CTA 128(M=s) x 128(N=e/o), K=512, fp16 mma.sync + cp.async
// grid: (64, 256): y = batch, x = nt*8 + mt;  nt 0-3 -> W_ref, 4-7 -> conv_w
// smem 66.5KB -> 2 CTAs/SM. Conv transpose reuses stage smem in 2 halves.
// ---------------------------------------------------------------------------
#define STAGES      4
#define STAGE_BYTES 16384                       // A 8KB + B 8KB
#define C_PITCH     132
#define SM_QV       (STAGES * STAGE_BYTES)      // 65536
#define SMEM_TOTAL  (SM_QV + 1024)              // 66560

extern __shared__ char dsm[];

__global__ void __launch_bounds__(256, 2)
gemm_kernel(const float* __restrict__ conv_b,
            const float* __restrict__ v,
            float* __restrict__ out_attn) {
    const uint32_t smb = smem_u32(dsm);
    const int tid  = threadIdx.x;
    const int wid  = tid >> 5;
    const int lane = tid & 31;
    const int wm   = wid & 3;          // 4 m-groups of 32 rows
    const int wn   = wid >> 2;         // 2 n-groups of 64 cols

    const int b  = blockIdx.y;
    const int nt = blockIdx.x >> 3;
    const int mt = blockIdx.x & 7;
    const int s0 = mt * 128;
    const int n0 = nt * 128;
    const bool is_ref = (nt < 4);

    float* sQ = reinterpret_cast<float*>(dsm + SM_QV);        // 128 floats
    float* sV = reinterpret_cast<float*>(dsm + SM_QV + 512);  // 128 floats
    float* sC = reinterpret_cast<float*>(dsm);                // reuse stages post-mainloop

    if (tid < 128) {
        if (is_ref) {
            sQ[tid] = g_q_buf[(size_t)b * DIM + n0 + tid];
            sV[tid] = v[n0 + tid];
        } else {
            sQ[tid] = conv_b[(n0 - 512) + tid];
        }
    }

    const __half* gA = g_src16 + ((size_t)b * SRCN + s0) * DIM;
    const __half* gB = g_w16 + (size_t)n0 * DIM;

    const int crow = tid >> 2;         // 0..63
    const int cch  = tid & 3;          // 16B chunk in 64B row

    float cacc[2][8][4];
#pragma unroll
    for (int i = 0; i < 2; i++)
#pragma unroll
        for (int j = 0; j < 8; j++)
#pragma unroll
            for (int r = 0; r < 4; r++) cacc[i][j][r] = 0.f;

    const int a_rl = lane & 15;
    const int a_ch = lane >> 4;
    const int b_rl = (lane & 7) | (((lane >> 4) & 1) << 3);
    const int b_ch = (lane >> 3) & 1;

    const int arow0 = wm * 32 + a_rl;
    const int arow1 = arow0 + 16;
    const int ax0 = (arow0 >> 1) & 3;
    const int ax1 = (arow1 >> 1) & 3;

    auto load_stage = [&](int st, int kt) {
        uint32_t base = smb + st * STAGE_BYTES;
        const __half* ga = gA + kt * 32;
        const __half* gb = gB + kt * 32;
#pragma unroll
        for (int p = 0; p < 2; p++) {
            int r = crow + p * 64;
            int swc = cch ^ ((r >> 1) & 3);
            CP_ASYNC16(base + r * 64 + swc * 16, ga + (size_t)r * DIM + cch * 8);
        }
#pragma unroll
        for (int p = 0; p < 2; p++) {
            int r = crow + p * 64;
            int swc = cch ^ ((r >> 1) & 3);
            CP_ASYNC16(base + 8192 + r * 64 + swc * 16, gb + (size_t)r * DIM + cch * 8);
        }
    };

    load_stage(0, 0); CP_COMMIT();
    load_stage(1, 1); CP_COMMIT();
    load_stage(2, 2); CP_COMMIT();

    for (int kt = 0; kt < 16; kt++) {
        CP_WAIT2();
        __syncthreads();
        if (kt + 3 < 16) load_stage((kt + 3) & 3, kt + 3);
        CP_COMMIT();

        uint32_t abase = smb + (kt & 3) * STAGE_BYTES;
        uint32_t bbase = abase + 8192;

#pragma unroll
        for (int kk = 0; kk < 2; kk++) {
            uint32_t a[2][4];
            {
                int c0 = (kk * 2 + a_ch) ^ ax0;
                ldsm4(a[0][0], a[0][1], a[0][2], a[0][3], abase + arow0 * 64 + c0 * 16);
                int c1 = (kk * 2 + a_ch) ^ ax1;
                ldsm4(a[1][0], a[1][1], a[1][2], a[1][3], abase + arow1 * 64 + c1 * 16);
            }
            uint32_t bb[4][4];
#pragma unroll
            for (int jj = 0; jj < 4; jj++) {
                int brow = wn * 64 + jj * 16 + b_rl;
                int c = (kk * 2 + b_ch) ^ ((brow >> 1) & 3);
                ldsm4(bb[jj][0], bb[jj][1], bb[jj][2], bb[jj][3], bbase + brow * 64 + c * 16);
            }
#pragma unroll
            for (int i = 0; i < 2; i++)
#pragma unroll
                for (int j = 0; j < 8; j++) {
                    int jj = j >> 1;
                    if (j & 1)
                        mma_f16(cacc[i][j], a[i][0], a[i][1], a[i][2], a[i][3], bb[jj][2], bb[jj][3]);
                    else
                        mma_f16(cacc[i][j], a[i][0], a[i][1], a[i][2], a[i][3], bb[jj][0], bb[jj][1]);
                }
        }
    }

    // ------------------------- epilogues -------------------------
    if (is_ref) {
        const int q = lane >> 2;
        const int cl = (lane & 3) * 2;
#pragma unroll
        for (int i = 0; i < 2; i++) {
            float p0 = 0.f, p1 = 0.f;
#pragma unroll
            for (int j = 0; j < 8; j++) {
                int el = wn * 64 + j * 8 + cl;
                float v0 = sV[el], v1 = sV[el + 1];
                float q0 = sQ[el], q1 = sQ[el + 1];
                p0 += v0 * ftanh(q0 + cacc[i][j][0]) + v1 * ftanh(q1 + cacc[i][j][1]);
                p1 += v0 * ftanh(q0 + cacc[i][j][2]) + v1 * ftanh(q1 + cacc[i][j][3]);
            }
            p0 += __shfl_xor_sync(0xffffffffu, p0, 1);
            p0 += __shfl_xor_sync(0xffffffffu, p0, 2);
            p1 += __shfl_xor_sync(0xffffffffu, p1, 1);
            p1 += __shfl_xor_sync(0xffffffffu, p1, 2);
            if ((lane & 3) == 0) {
                int r0 = wm * 32 + i * 16 + q;
                size_t idx = (((size_t)b * SRCN + s0 + r0) << 3) + nt * 2 + wn;
                g_u_part[idx] = p0;
                g_u_part[idx + (8ull << 3)] = p1;
            }
        }
    } else {
        // transpose via reused stage smem, two 64-col halves
        const int q = lane >> 2;
        const int cl = (lane & 3) * 2;
        const int o0 = n0 - 512;
        float* outb = out_attn + ((size_t)b * DIM + o0) * SRCN + s0;
#pragma unroll
        for (int h = 0; h < 2; h++) {
            __syncthreads();   // stage smem free (mainloop or prev half done)
            if (wn == h) {
#pragma unroll
                for (int i = 0; i < 2; i++) {
                    int r0 = wm * 32 + i * 16 + q;
#pragma unroll
                    for (int j = 0; j < 8; j++) {
                        int o = j * 8 + cl;   // local 0..63
                        sC[o * C_PITCH + r0]           = cacc[i][j][0];
                        sC[(o + 1) * C_PITCH + r0]     = cacc[i][j][1];
                        sC[o * C_PITCH + r0 + 8]       = cacc[i][j][2];
                        sC[(o + 1) * C_PITCH + r0 + 8] = cacc[i][j][3];
                    }
                }
            }
            __syncthreads();
#pragma unroll 2
            for (int it = tid; it < 64 * 32; it += 256) {
                int o = it >> 5;
                int sq = (it & 31) * 4;
                float4 val = *reinterpret_cast<const float4*>(sC + o * C_PITCH + sq);
                float bias = sQ[h * 64 + o];
                val.x += bias; val.y += bias; val.z += bias; val.w += bias;
                *reinterpret_cast<float4*>(outb + (size_t)(h * 64 + o) * SRCN + sq) = val;
            }
        }
    }
}

// ---------------------------------------------------------------------------
// softmax: u = sum(8 partials); score=C*tanh(u); mask; softmax; outputs
// ---------------------------------------------------------------------------
__global__ void softmax_kernel(const uint8_t* __restrict__ mask_in,
                               const int* __restrict__ prev,
                               float* __restrict__ out,
                               int has_logits, int has_mask) {
    __shared__ float red[256];
    const int b = blockIdx.x, tid = threadIdx.x;
    const int p = prev[b];

    float sc[4];
    bool  ms[4];
    float mx = -3.0e38f;
#pragma unroll
    for (int j = 0; j < 4; j++) {
        int s = tid + j * 256;
        const float* up = g_u_part + (((size_t)b * SRCN + s) << 3);
        float u = 0.f;
#pragma unroll
        for (int k = 0; k < 8; k++) u += up[k];
        bool m = (mask_in[(size_t)b * SRCN + s] != 0) || (s == p);
        ms[j] = m;
        float val = m ? -3.0e38f : 10.f * tanhf(u);
        sc[j] = val;
        mx = fmaxf(mx, val);
    }
    red[tid] = mx; __syncthreads();
    for (int o = 128; o > 0; o >>= 1) {
        if (tid < o) red[tid] = fmaxf(red[tid], red[tid + o]);
        __syncthreads();
    }
    mx = red[0];
    __syncthreads();

    float e[4], se = 0.f;
#pragma unroll
    for (int j = 0; j < 4; j++) {
        e[j] = ms[j] ? 0.f : expf(sc[j] - mx);
        se += e[j];
    }
    red[tid] = se; __syncthreads();
    for (int o = 128; o > 0; o >>= 1) {
        if (tid < o) red[tid] += red[tid + o];
        __syncthreads();
    }
    const float inv = 1.f / red[0];

    const size_t attn = (size_t)BZ * DIM * SRCN;
#pragma unroll
    for (int j = 0; j < 4; j++) {
        int s = tid + j * 256;
        if (has_logits) out[attn + (size_t)b * SRCN + s] = e[j] * inv;
        if (has_mask)   out[attn + (size_t)BZ * SRCN + (size_t)b * SRCN + s] = ms[j] ? 1.f : 0.f;
    }
}

// ---------------------------------------------------------------------------
extern "C" void kernel_launch(void* const* d_in, const int* in_sizes, int n_in,
                              void* d_out, int out_size) {
    (void)in_sizes; (void)n_in;
    const float*   src    = (const float*)d_in[0];
    const float*   tgt    = (const float*)d_in[1];
    const uint8_t* mask   = (const uint8_t*)d_in[2];
    const int*     prev   = (const int*)d_in[3];
    const float*   W_q    = (const float*)d_in[4];
    const float*   W_ref  = (const float*)d_in[5];
    const float*   v      = (const float*)d_in[6];
    const float*   conv_w = (const float*)d_in[7];
    const float*   conv_b = (const float*)d_in[8];
    float* out = (float*)d_out;

    const size_t attn = (size_t)BZ * DIM * SRCN;
    const size_t row  = (size_t)BZ * SRCN;
    int has_logits = ((size_t)out_size >= attn + row)     ? 1 : 0;
    int has_mask   = ((size_t)out_size >= attn + 2 * row) ? 1 : 0;

    cudaFuncSetAttribute(gemm_kernel,
                         cudaFuncAttributeMaxDynamicSharedMemorySize, SMEM_TOTAL);

    convert_kernel<<<65792, 256>>>(src, W_ref, conv_w);
    qproj_kernel<<<64, 512>>>(tgt, W_q);

    dim3 grid(64, BZ);
    gemm_kernel<<<grid, 256, SMEM_TOTAL>>>(conv_b, v, out);

    softmax_kernel<<<BZ, 256>>>(mask, prev, out, has_logits, has_mask);
}

// round 5
// speedup vs baseline: 4.6285x; 1.0678x over previous
#include <cuda_runtime.h>
#include <cuda_fp16.h>
#include <cstdint>

#define BZ   256
#define SRCN 1024
#define DIM  512

// ---------------------------------------------------------------------------
// scratch (no cudaMalloc allowed)
// ---------------------------------------------------------------------------
__device__ __align__(16) __half g_src16[(size_t)BZ * SRCN * DIM];   // 268 MB
__device__ __align__(16) __half g_w16[1024 * DIM];                  // W_ref 0-511, conv_w 512-1023
__device__ __align__(16) float  g_q_buf[BZ * DIM];
__device__ __align__(16) float  g_u_part[(size_t)BZ * SRCN * 8];    // 8 partials per (b,s)

// ---------------------------------------------------------------------------
// helpers
// ---------------------------------------------------------------------------
__device__ __forceinline__ uint32_t smem_u32(const void* p) {
    uint32_t a;
    asm("{ .reg .u64 t; cvta.to.shared.u64 t, %1; cvt.u32.u64 %0, t; }" : "=r"(a) : "l"(p));
    return a;
}

#define CP_ASYNC16(dst, src) \
    asm volatile("cp.async.cg.shared.global [%0], [%1], 16;" :: "r"(dst), "l"(src))
#define CP_COMMIT() asm volatile("cp.async.commit_group;" ::: "memory")
#define CP_WAIT1()  asm volatile("cp.async.wait_group 1;" ::: "memory")

__device__ __forceinline__ void ldsm4(uint32_t& r0, uint32_t& r1, uint32_t& r2, uint32_t& r3,
                                      uint32_t addr) {
    asm volatile("ldmatrix.sync.aligned.m8n8.x4.shared.b16 {%0,%1,%2,%3}, [%4];"
                 : "=r"(r0), "=r"(r1), "=r"(r2), "=r"(r3) : "r"(addr));
}

__device__ __forceinline__ void mma_f16(float* c, uint32_t a0, uint32_t a1, uint32_t a2, uint32_t a3,
                                        uint32_t b0, uint32_t b1) {
    asm volatile("mma.sync.aligned.m16n8k16.row.col.f32.f16.f16.f32 "
                 "{%0,%1,%2,%3}, {%4,%5,%6,%7}, {%8,%9}, {%0,%1,%2,%3};"
                 : "+f"(c[0]), "+f"(c[1]), "+f"(c[2]), "+f"(c[3])
                 : "r"(a0), "r"(a1), "r"(a2), "r"(a3), "r"(b0), "r"(b1));
}

__device__ __forceinline__ float ftanh(float x) {
    float e = __expf(2.0f * x);
    return 1.0f - __fdividef(2.0f, e + 1.0f);
}

// ---------------------------------------------------------------------------
// convert fp32 -> fp16 (src + both weight matrices)
// ---------------------------------------------------------------------------
#define SRC_ELEMS ((size_t)BZ * SRCN * DIM)
#define W_ELEMS   (512 * 512)

__global__ void __launch_bounds__(256) convert_kernel(const float* __restrict__ src,
                                                      const float* __restrict__ W_ref,
                                                      const float* __restrict__ conv_w) {
    size_t gid = (size_t)blockIdx.x * 256 + threadIdx.x;
    size_t i8 = gid * 8;
    if (i8 < SRC_ELEMS) {
        float4 x0 = *reinterpret_cast<const float4*>(src + i8);
        float4 x1 = *reinterpret_cast<const float4*>(src + i8 + 4);
        __half2 h0 = __floats2half2_rn(x0.x, x0.y);
        __half2 h1 = __floats2half2_rn(x0.z, x0.w);
        __half2 h2 = __floats2half2_rn(x1.x, x1.y);
        __half2 h3 = __floats2half2_rn(x1.z, x1.w);
        uint4 o = make_uint4(*(uint32_t*)&h0, *(uint32_t*)&h1, *(uint32_t*)&h2, *(uint32_t*)&h3);
        *reinterpret_cast<uint4*>(g_src16 + i8) = o;
    } else {
        size_t w8 = i8 - SRC_ELEMS;
        if (w8 < 2 * (size_t)W_ELEMS) {
            const float* wsrc = (w8 < W_ELEMS) ? (W_ref + w8) : (conv_w + (w8 - W_ELEMS));
            float4 x0 = *reinterpret_cast<const float4*>(wsrc);
            float4 x1 = *reinterpret_cast<const float4*>(wsrc + 4);
            __half2 h0 = __floats2half2_rn(x0.x, x0.y);
            __half2 h1 = __floats2half2_rn(x0.z, x0.w);
            __half2 h2 = __floats2half2_rn(x1.x, x1.y);
            __half2 h3 = __floats2half2_rn(x1.z, x1.w);
            uint4 o = make_uint4(*(uint32_t*)&h0, *(uint32_t*)&h1, *(uint32_t*)&h2, *(uint32_t*)&h3);
            *reinterpret_cast<uint4*>(g_w16 + w8) = o;
        }
    }
}

// ---------------------------------------------------------------------------
// qproj: q[b,e] = sum_d tgt[b,d] * W_q[e,d]
// ---------------------------------------------------------------------------
__global__ void __launch_bounds__(512) qproj_kernel(const float* __restrict__ tgt,
                                                    const float* __restrict__ Wq) {
    __shared__ float st[4 * DIM];
    const int b0 = blockIdx.x * 4;
    const int tid = threadIdx.x;
    for (int i = tid; i < 4 * DIM; i += 512) st[i] = tgt[(size_t)b0 * DIM + i];
    __syncthreads();
    const float4* w = reinterpret_cast<const float4*>(Wq + (size_t)tid * DIM);
    const float4* t0 = reinterpret_cast<const float4*>(st);
    const float4* t1 = reinterpret_cast<const float4*>(st + DIM);
    const float4* t2 = reinterpret_cast<const float4*>(st + 2 * DIM);
    const float4* t3 = reinterpret_cast<const float4*>(st + 3 * DIM);
    float a0 = 0.f, a1 = 0.f, a2 = 0.f, a3 = 0.f;
#pragma unroll 4
    for (int i = 0; i < DIM / 4; i++) {
        float4 wv = w[i];
        float4 c;
        c = t0[i]; a0 += wv.x*c.x + wv.y*c.y + wv.z*c.z + wv.w*c.w;
        c = t1[i]; a1 += wv.x*c.x + wv.y*c.y + wv.z*c.z + wv.w*c.w;
        c = t2[i]; a2 += wv.x*c.x + wv.y*c.y + wv.z*c.z + wv.w*c.w;
        c = t3[i]; a3 += wv.x*c.x + wv.y*c.y + wv.z*c.z + wv.w*c.w;
    }
    g_q_buf[(size_t)(b0 + 0) * DIM + tid] = a0;
    g_q_buf[(size_t)(b0 + 1) * DIM + tid] = a1;
    g_q_buf[(size_t)(b0 + 2) * DIM + tid] = a2;
    g_q_buf[(size_t)(b0 + 3) * DIM + tid] = a3;
}

// ---------------------------------------------------------------------------
// main GEMM: per CTA 128(M=s) x 128(N=e/o), K=512, fp16 mma.sync + cp.async
// K-tile 64, 3 stages of 32KB (A 16KB + B 16KB), 2 CTAs/SM, 8 mainloop syncs
// grid: (64, 256): y = batch, x = nt*8 + mt;  nt 0-3 -> W_ref, 4-7 -> conv_w
// ---------------------------------------------------------------------------
#define KT          64
#define NKT         8                            // 512/64
#define STAGES      3
#define STAGE_BYTES 32768                        // A 16KB + B 16KB
#define C_PITCH     132
#define SM_QV       (STAGES * STAGE_BYTES)       // 98304
#define SMEM_TOTAL  (SM_QV + 1024)               // 99328

extern __shared__ char dsm[];

__global__ void __launch_bounds__(256, 2)
gemm_kernel(const float* __restrict__ conv_b,
            const float* __restrict__ v,
            float* __restrict__ out_attn) {
    const uint32_t smb = smem_u32(dsm);
    const int tid  = threadIdx.x;
    const int wid  = tid >> 5;
    const int lane = tid & 31;
    const int wm   = wid & 3;          // 4 m-groups of 32 rows
    const int wn   = wid >> 2;         // 2 n-groups of 64 cols

    const int b  = blockIdx.y;
    const int nt = blockIdx.x >> 3;
    const int mt = blockIdx.x & 7;
    const int s0 = mt * 128;
    const int n0 = nt * 128;
    const bool is_ref = (nt < 4);

    float* sQ = reinterpret_cast<float*>(dsm + SM_QV);        // 128 floats
    float* sV = reinterpret_cast<float*>(dsm + SM_QV + 512);  // 128 floats
    float* sC = reinterpret_cast<float*>(dsm);                // reuse stages post-mainloop

    if (tid < 128) {
        if (is_ref) {
            sQ[tid] = g_q_buf[(size_t)b * DIM + n0 + tid];
            sV[tid] = v[n0 + tid];
        } else {
            sQ[tid] = conv_b[(n0 - 512) + tid];
        }
    }

    const __half* gA = g_src16 + ((size_t)b * SRCN + s0) * DIM;
    const __half* gB = g_w16 + (size_t)n0 * DIM;

    // cp.async coords: 128 rows x 8 chunks of 16B per tile, 256 threads
    const int crow = tid >> 3;         // 0..31
    const int ccol = tid & 7;          // chunk in 128B row

    float cacc[2][8][4];
#pragma unroll
    for (int i = 0; i < 2; i++)
#pragma unroll
        for (int j = 0; j < 8; j++)
#pragma unroll
            for (int r = 0; r < 4; r++) cacc[i][j][r] = 0.f;

    const int a_rl = lane & 15;
    const int a_ch = lane >> 4;
    const int b_rl = (lane & 7) | (((lane >> 4) & 1) << 3);
    const int b_ch = (lane >> 3) & 1;

    const int arow0 = wm * 32 + a_rl;
    const int arow1 = arow0 + 16;
    const int ax0 = arow0 & 7;
    const int ax1 = arow1 & 7;

    auto load_stage = [&](int st, int kt) {
        uint32_t base = smb + st * STAGE_BYTES;
        const __half* ga = gA + kt * KT;
        const __half* gb = gB + kt * KT;
#pragma unroll
        for (int p = 0; p < 4; p++) {
            int r = crow + p * 32;
            int swc = ccol ^ (r & 7);
            CP_ASYNC16(base + r * 128 + swc * 16, ga + (size_t)r * DIM + ccol * 8);
        }
#pragma unroll
        for (int p = 0; p < 4; p++) {
            int r = crow + p * 32;
            int swc = ccol ^ (r & 7);
            CP_ASYNC16(base + 16384 + r * 128 + swc * 16, gb + (size_t)r * DIM + ccol * 8);
        }
    };

    load_stage(0, 0); CP_COMMIT();
    load_stage(1, 1); CP_COMMIT();

    uint32_t a[2][4];
    uint32_t bb[4][4];

    for (int kt = 0; kt < NKT; kt++) {
        CP_WAIT1();
        __syncthreads();
        if (kt + 2 < NKT) load_stage((kt + 2) % 3, kt + 2);
        CP_COMMIT();

        uint32_t abase = smb + (kt % 3) * STAGE_BYTES;
        uint32_t bbase = abase + 16384;

#pragma unroll
        for (int kk = 0; kk < 4; kk++) {
            {
                int c0 = (kk * 2 + a_ch) ^ ax0;
                ldsm4(a[0][0], a[0][1], a[0][2], a[0][3], abase + arow0 * 128 + c0 * 16);
                int c1 = (kk * 2 + a_ch) ^ ax1;
                ldsm4(a[1][0], a[1][1], a[1][2], a[1][3], abase + arow1 * 128 + c1 * 16);
            }
#pragma unroll
            for (int jj = 0; jj < 4; jj++) {
                int brow = wn * 64 + jj * 16 + b_rl;
                int c = (kk * 2 + b_ch) ^ (brow & 7);
                ldsm4(bb[jj][0], bb[jj][1], bb[jj][2], bb[jj][3], bbase + brow * 128 + c * 16);
            }
#pragma unroll
            for (int i = 0; i < 2; i++)
#pragma unroll
                for (int j = 0; j < 8; j++) {
                    int jj = j >> 1;
                    if (j & 1)
                        mma_f16(cacc[i][j], a[i][0], a[i][1], a[i][2], a[i][3], bb[jj][2], bb[jj][3]);
                    else
                        mma_f16(cacc[i][j], a[i][0], a[i][1], a[i][2], a[i][3], bb[jj][0], bb[jj][1]);
                }
        }
    }

    // ------------------------- epilogues -------------------------
    if (is_ref) {
        const int q = lane >> 2;
        const int cl = (lane & 3) * 2;
#pragma unroll
        for (int i = 0; i < 2; i++) {
            float p0 = 0.f, p1 = 0.f;
#pragma unroll
            for (int j = 0; j < 8; j++) {
                int el = wn * 64 + j * 8 + cl;
                float v0 = sV[el], v1 = sV[el + 1];
                float q0 = sQ[el], q1 = sQ[el + 1];
                p0 += v0 * ftanh(q0 + cacc[i][j][0]) + v1 * ftanh(q1 + cacc[i][j][1]);
                p1 += v0 * ftanh(q0 + cacc[i][j][2]) + v1 * ftanh(q1 + cacc[i][j][3]);
            }
            p0 += __shfl_xor_sync(0xffffffffu, p0, 1);
            p0 += __shfl_xor_sync(0xffffffffu, p0, 2);
            p1 += __shfl_xor_sync(0xffffffffu, p1, 1);
            p1 += __shfl_xor_sync(0xffffffffu, p1, 2);
            if ((lane & 3) == 0) {
                int r0 = wm * 32 + i * 16 + q;
                size_t idx = (((size_t)b * SRCN + s0 + r0) << 3) + nt * 2 + wn;
                g_u_part[idx] = p0;
                g_u_part[idx + (8ull << 3)] = p1;
            }
        }
    } else {
        const int q = lane >> 2;
        const int cl = (lane & 3) * 2;
        const int o0 = n0 - 512;
        float* outb = out_attn + ((size_t)b * DIM + o0) * SRCN + s0;
#pragma unroll
        for (int h = 0; h < 2; h++) {
            __syncthreads();
            if (wn == h) {
#pragma unroll
                for (int i = 0; i < 2; i++) {
                    int r0 = wm * 32 + i * 16 + q;
#pragma unroll
                    for (int j = 0; j < 8; j++) {
                        int o = j * 8 + cl;
                        sC[o * C_PITCH + r0]           = cacc[i][j][0];
                        sC[(o + 1) * C_PITCH + r0]     = cacc[i][j][1];
                        sC[o * C_PITCH + r0 + 8]       = cacc[i][j][2];
                        sC[(o + 1) * C_PITCH + r0 + 8] = cacc[i][j][3];
                    }
                }
            }
            __syncthreads();
#pragma unroll 2
            for (int it = tid; it < 64 * 32; it += 256) {
                int o = it >> 5;
                int sq = (it & 31) * 4;
                float4 val = *reinterpret_cast<const float4*>(sC + o * C_PITCH + sq);
                float bias = sQ[h * 64 + o];
                val.x += bias; val.y += bias; val.z += bias; val.w += bias;
                *reinterpret_cast<float4*>(outb + (size_t)(h * 64 + o) * SRCN + sq) = val;
            }
        }
    }
}

// ---------------------------------------------------------------------------
// softmax: u = sum(8 partials); score=C*tanh(u); mask; softmax; outputs
// ---------------------------------------------------------------------------
__global__ void softmax_kernel(const uint8_t* __restrict__ mask_in,
                               const int* __restrict__ prev,
                               float* __restrict__ out,
                               int has_logits, int has_mask) {
    __shared__ float red[256];
    const int b = blockIdx.x, tid = threadIdx.x;
    const int p = prev[b];

    float sc[4];
    bool  ms[4];
    float mx = -3.0e38f;
#pragma unroll
    for (int j = 0; j < 4; j++) {
        int s = tid + j * 256;
        const float* up = g_u_part + (((size_t)b * SRCN + s) << 3);
        float u = 0.f;
#pragma unroll
        for (int k = 0; k < 8; k++) u += up[k];
        bool m = (mask_in[(size_t)b * SRCN + s] != 0) || (s == p);
        ms[j] = m;
        float val = m ? -3.0e38f : 10.f * tanhf(u);
        sc[j] = val;
        mx = fmaxf(mx, val);
    }
    red[tid] = mx; __syncthreads();
    for (int o = 128; o > 0; o >>= 1) {
        if (tid < o) red[tid] = fmaxf(red[tid], red[tid + o]);
        __syncthreads();
    }
    mx = red[0];
    __syncthreads();

    float e[4], se = 0.f;
#pragma unroll
    for (int j = 0; j < 4; j++) {
        e[j] = ms[j] ? 0.f : expf(sc[j] - mx);
        se += e[j];
    }
    red[tid] = se; __syncthreads();
    for (int o = 128; o > 0; o >>= 1) {
        if (tid < o) red[tid] += red[tid + o];
        __syncthreads();
    }
    const float inv = 1.f / red[0];

    const size_t attn = (size_t)BZ * DIM * SRCN;
#pragma unroll
    for (int j = 0; j < 4; j++) {
        int s = tid + j * 256;
        if (has_logits) out[attn + (size_t)b * SRCN + s] = e[j] * inv;
        if (has_mask)   out[attn + (size_t)BZ * SRCN + (size_t)b * SRCN + s] = ms[j] ? 1.f : 0.f;
    }
}

// ---------------------------------------------------------------------------
extern "C" void kernel_launch(void* const* d_in, const int* in_sizes, int n_in,
                              void* d_out, int out_size) {
    (void)in_sizes; (void)n_in;
    const float*   src    = (const float*)d_in[0];
    const float*   tgt    = (const float*)d_in[1];
    const uint8_t* mask   = (const uint8_t*)d_in[2];
    const int*     prev   = (const int*)d_in[3];
    const float*   W_q    = (const float*)d_in[4];
    const float*   W_ref  = (const float*)d_in[5];
    const float*   v      = (const float*)d_in[6];
    const float*   conv_w = (const float*)d_in[7];
    const float*   conv_b = (const float*)d_in[8];
    float* out = (float*)d_out;

    const size_t attn = (size_t)BZ * DIM * SRCN;
    const size_t row  = (size_t)BZ * SRCN;
    int has_logits = ((size_t)out_size >= attn + row)     ? 1 : 0;
    int has_mask   = ((size_t)out_size >= attn + 2 * row) ? 1 : 0;

    cudaFuncSetAttribute(gemm_kernel,
                         cudaFuncAttributeMaxDynamicSharedMemorySize, SMEM_TOTAL);

    convert_kernel<<<65792, 256>>>(src, W_ref, conv_w);
    qproj_kernel<<<64, 512>>>(tgt, W_q);

    dim3 grid(64, BZ);
    gemm_kernel<<<grid, 256, SMEM_TOTAL>>>(conv_b, v, out);

    softmax_kernel<<<BZ, 256>>>(mask, prev, out, has_logits, has_mask);
}